// round 17
// baseline (speedup 1.0000x reference)
#include <cuda_runtime.h>
#include <stdint.h>

// Unpack padded [B, Lmax, H, D] fp32 -> packed [N, H, D], N = sum(lengths).
// Row = H*D = 2048 floats = 512 float4 = 8 KB.
//
// v9: same proven structure (two-phase register copy, front-batched MLP 8,
// .cs both ways) at a new block geometry: 512 threads x 8 rows/block.
// Per-thread MLP stays 8 (1 float4/thread/row), regs ~40, but the per-byte
// (b,t) resolve ALU halves and block count halves (1952). Copy/coalescing
// pattern per warp is unchanged (512 B contiguous per LDG.128).
//
// Roofline context (matched pairs R7-R16): the 256-thread form pins at
// 36.5-36.9 us ~= 244 MB bidir at 6.6 TB/s (~83% HBM spec). MLP 16,
// cp.async, work-stealing, branch-free, .wt and write-back stores all
// measured equal or worse.
//
// lengths dtype detected on-device (JAX x64-off downcasts int64 -> int32):
// parse as contiguous int32 AND int64-low-words; whichever sums to N wins.

#define ROW_VEC4        512          // float4 per row
#define THREADS         512
#define ROWS_PER_BLOCK  8
#define MAX_B           32

__global__ void __launch_bounds__(THREADS) unpack_rows8x512_kernel(
    const float4* __restrict__ in,        // [B, Lmax, 512] as float4
    const int* __restrict__ lengths_raw,  // [B] raw words
    float4* __restrict__ out,             // [N, 512] as float4
    int B, int Lmax, int N)
{
    const int n0 = blockIdx.x * ROWS_PER_BLOCK;
    const int tx = threadIdx.x;

    // --- dtype detection (B tiny; L1-resident, uniform across threads) ---
    long long sum32 = 0, sum64 = 0;
    #pragma unroll 8
    for (int i = 0; i < B; ++i) {
        sum32 += __ldg(&lengths_raw[i]);
        sum64 += __ldg(&lengths_raw[2 * i]);
    }
    const bool is64 = (sum64 == (long long)N) && (sum32 != (long long)N);

    // --- resolve source offsets (float4 units) for the 8 rows ---
    int srcOff[ROWS_PER_BLOCK];
    bool valid[ROWS_PER_BLOCK];
    #pragma unroll
    for (int r = 0; r < ROWS_PER_BLOCK; ++r) {
        const int n = n0 + r;
        valid[r] = (n < N);
        int s = 0, b = 0, t = 0;
        #pragma unroll 8
        for (int i = 0; i < B; ++i) {
            const int len = is64 ? __ldg(&lengths_raw[2 * i]) : __ldg(&lengths_raw[i]);
            if (n >= s && n < s + len) { b = i; t = n - s; }
            s += len;
        }
        srcOff[r] = (b * Lmax + t) * ROW_VEC4;   // < 16.8M, fits int
    }

    // --- phase 1: 8 independent streaming loads (front-batched, MLP 8) ---
    float4 v[ROWS_PER_BLOCK];
    #pragma unroll
    for (int r = 0; r < ROWS_PER_BLOCK; ++r)
        if (valid[r])
            v[r] = __ldcs(&in[srcOff[r] + tx]);

    // --- phase 2: 8 streaming stores ---
    #pragma unroll
    for (int r = 0; r < ROWS_PER_BLOCK; ++r)
        if (valid[r])
            __stcs(&out[(size_t)(n0 + r) * ROW_VEC4 + tx], v[r]);
}

extern "C" void kernel_launch(void* const* d_in, const int* in_sizes, int n_in,
                              void* d_out, int out_size)
{
    const float4* packed = (const float4*)d_in[0];   // [B, Lmax, H, D] fp32
    const int* lengths_raw = (const int*)d_in[1];    // [B] (int32 or int64 words)

    int B = in_sizes[1];
    if (B > MAX_B) B = MAX_B;
    long long total_in = in_sizes[0];                     // B*Lmax*2048 floats
    int Lmax = (int)(total_in / ((long long)B * 2048));   // 4096

    int N = out_size / 2048;                              // packed rows

    float4* out = (float4*)d_out;

    int grid = (N + ROWS_PER_BLOCK - 1) / ROWS_PER_BLOCK;
    if (grid < 1) grid = 1;
    unpack_rows8x512_kernel<<<grid, THREADS>>>(packed, lengths_raw, out,
                                               B, Lmax, N);
}